// round 2
// baseline (speedup 1.0000x reference)
#include <cuda_runtime.h>
#include <math.h>

#define Hdim 4096
#define Edim 64
#define TM   64     // tokens per CTA
#define KC   32     // k-chunk
#define PITCH 65    // TM+1 (bank-conflict-free transposed layout)

__global__ __launch_bounds__(256, 2)
void router_kernel(const float* __restrict__ x,
                   const float* __restrict__ W,
                   float* __restrict__ out, int T)
{
    // sh is reused: phase 1 = xs[KC][PITCH] + ws[KC][PITCH]; phase 2 = logits ls[TM][PITCH]
    __shared__ float sh[TM * PITCH];           // 4160 floats = 16640 B
    __shared__ float s_max[TM];
    __shared__ float s_inv[TM];

    float* xs = sh;                 // xs[k*PITCH + t]
    float* ws = sh + KC * PITCH;    // ws[k*PITCH + e]

    const int tid = threadIdx.x;
    const int tb  = blockIdx.x * TM;           // token base

    const int lk = tid & 31;        // k index for loads
    const int lr = tid >> 5;        // row (token/expert) base for loads, 8 rows/pass

    const int tx4 = (tid & 15) * 4; // expert block (4 experts)
    const int ty4 = (tid >> 4) * 4; // token block (4 tokens)

    float acc[4][4];
#pragma unroll
    for (int i = 0; i < 4; i++)
#pragma unroll
        for (int j = 0; j < 4; j++) acc[i][j] = 0.0f;

    for (int kb = 0; kb < Hdim; kb += KC) {
        __syncthreads();   // previous chunk's shared reads done
        // load x tile: 64 tokens x 32 k  (coalesced 128B per warp)
#pragma unroll
        for (int p = 0; p < 8; p++) {
            int t = lr + p * 8;
            xs[lk * PITCH + t] = x[(size_t)(tb + t) * Hdim + kb + lk];
        }
        // load W tile: 64 experts x 32 k
#pragma unroll
        for (int p = 0; p < 8; p++) {
            int e = lr + p * 8;
            ws[lk * PITCH + e] = W[(size_t)e * Hdim + kb + lk];
        }
        __syncthreads();

#pragma unroll 8
        for (int k = 0; k < KC; k++) {
            float a0 = xs[k * PITCH + ty4 + 0];
            float a1 = xs[k * PITCH + ty4 + 1];
            float a2 = xs[k * PITCH + ty4 + 2];
            float a3 = xs[k * PITCH + ty4 + 3];
            float b0 = ws[k * PITCH + tx4 + 0];
            float b1 = ws[k * PITCH + tx4 + 1];
            float b2 = ws[k * PITCH + tx4 + 2];
            float b3 = ws[k * PITCH + tx4 + 3];
            acc[0][0] += a0 * b0; acc[0][1] += a0 * b1; acc[0][2] += a0 * b2; acc[0][3] += a0 * b3;
            acc[1][0] += a1 * b0; acc[1][1] += a1 * b1; acc[1][2] += a1 * b2; acc[1][3] += a1 * b3;
            acc[2][0] += a2 * b0; acc[2][1] += a2 * b1; acc[2][2] += a2 * b2; acc[2][3] += a2 * b3;
            acc[3][0] += a3 * b0; acc[3][1] += a3 * b1; acc[3][2] += a3 * b2; acc[3][3] += a3 * b3;
        }
    }

    // ---- epilogue: stash logits in shared, fused softmax + top-2 ----
    __syncthreads();   // all compute reads of xs/ws done before overwrite
    float* ls = sh;    // ls[t*PITCH + e]
#pragma unroll
    for (int i = 0; i < 4; i++)
#pragma unroll
        for (int j = 0; j < 4; j++)
            ls[(ty4 + i) * PITCH + tx4 + j] = acc[i][j];
    __syncthreads();

    float* scores_out = out;
    float* w_out = out + (size_t)T * Edim;
    float* i_out = w_out + (size_t)T * 2;

    if (tid < TM) {
        const float* row = ls + tid * PITCH;
        float m = -INFINITY;
#pragma unroll
        for (int e = 0; e < Edim; e++) m = fmaxf(m, row[e]);

        float ssum = 0.0f;
        float v0 = -INFINITY, v1 = -INFINITY;
        int   i0 = 0, i1 = 0;
#pragma unroll
        for (int e = 0; e < Edim; e++) {
            float v = row[e];
            ssum += expf(v - m);
            if (v > v0) { v1 = v0; i1 = i0; v0 = v; i0 = e; }
            else if (v > v1) { v1 = v; i1 = e; }
        }
        s_max[tid] = m;
        s_inv[tid] = 1.0f / ssum;

        // top-2 weights normalized by their own sum (p=1 norm of positive vals)
        float e0 = expf(v0 - m);
        float e1 = expf(v1 - m);
        float rs = 1.0f / (e0 + e1);
        size_t gt = (size_t)(tb + tid);
        w_out[gt * 2 + 0] = e0 * rs;
        w_out[gt * 2 + 1] = e1 * rs;
        i_out[gt * 2 + 0] = (float)i0;
        i_out[gt * 2 + 1] = (float)i1;
    }
    __syncthreads();

    // scores: all 256 threads, coalesced over expert dim
#pragma unroll
    for (int idx = tid; idx < TM * Edim; idx += 256) {
        int t = idx >> 6;
        int e = idx & 63;
        scores_out[(size_t)(tb + t) * Edim + e] =
            expf(ls[t * PITCH + e] - s_max[t]) * s_inv[t];
    }
}

extern "C" void kernel_launch(void* const* d_in, const int* in_sizes, int n_in,
                              void* d_out, int out_size)
{
    const float* x = (const float*)d_in[0];
    const float* W = (const float*)d_in[1];
    float* out = (float*)d_out;
    int T = in_sizes[0] / Hdim;         // 16384
    router_kernel<<<T / TM, 256>>>(x, W, out, T);
}

// round 6
// speedup vs baseline: 1.1239x; 1.1239x over previous
#include <cuda_runtime.h>
#include <math.h>
#include <stdint.h>

#define Hdim   4096
#define Edim   64
#define TOKS   128                  // tokens per CTA
#define KC     32                   // K elems per chunk (128 B per row)
#define NCHUNK (Hdim / KC)          // 128
#define A_BYTES (TOKS * KC * 4)     // 16384
#define B_BYTES (Edim * KC * 4)     // 8192
#define TILE_BYTES (A_BYTES + B_BYTES)  // 24576
#define RAW_N  3
#define LO_OFF (RAW_N * TILE_BYTES)
#define DYN_SMEM (RAW_N * TILE_BYTES + 2 * TILE_BYTES)   // 122880 B
#define LPITCH 72
#define TAU 4e-3f

#define MMA(d, a, b)                                                          \
    asm volatile("mma.sync.aligned.m16n8k8.row.col.f32.tf32.tf32.f32 "        \
                 "{%0,%1,%2,%3},{%4,%5,%6,%7},{%8,%9},{%0,%1,%2,%3};"         \
                 : "+f"((d)[0]), "+f"((d)[1]), "+f"((d)[2]), "+f"((d)[3])     \
                 : "r"((a)[0]), "r"((a)[1]), "r"((a)[2]), "r"((a)[3]),        \
                   "r"((b)[0]), "r"((b)[1]))

__device__ int  g_qcount;
__device__ int2 g_qitems[16384];

__device__ __forceinline__ void cp16(uint32_t dst, const void* src) {
    asm volatile("cp.async.cg.shared.global [%0], [%1], 16;" :: "r"(dst), "l"(src));
}

__global__ __launch_bounds__(256, 1)
void router_mma(const float* __restrict__ x, const float* __restrict__ W,
                float* __restrict__ out, int T)
{
    extern __shared__ __align__(16) char dsm[];
    __shared__ float s_max[TOKS];
    __shared__ float s_inv[TOKS];

    const int tid  = threadIdx.x;
    const int wid  = tid >> 5;
    const int lane = tid & 31;
    const int q    = lane >> 2;      // group id (row)
    const int cc   = lane & 3;       // thread-in-group (k)
    const int wm   = wid >> 1;       // 0..3  (M tile: 32 tokens)
    const int wn   = wid & 1;        // 0..1  (N tile: 32 experts)
    const int tb   = blockIdx.x * TOKS;

    const uint32_t sbase = (uint32_t)__cvta_generic_to_shared(dsm);

    // -------- chunk loader: interleaved layout [k/4][row][k%4], cp.async 16B --------
    auto load_chunk = [&](int c, int b) {
        const uint32_t rb = sbase + b * TILE_BYTES;
        const int kb = c * KC;
#pragma unroll
        for (int p = 0; p < 4; p++) {            // A: 1024 segs of 16B
            int i  = tid + p * 256;
            int r  = i >> 3, s4 = i & 7;
            cp16(rb + s4 * 2048 + r * 16,
                 x + (size_t)(tb + r) * Hdim + kb + s4 * 4);
        }
#pragma unroll
        for (int p = 0; p < 2; p++) {            // B: 512 segs of 16B
            int i  = tid + p * 256;
            int e  = i >> 3, s4 = i & 7;
            cp16(rb + A_BYTES + s4 * 1024 + e * 16,
                 W + (size_t)e * Hdim + kb + s4 * 4);
        }
        asm volatile("cp.async.commit_group;" ::: "memory");
    };

    float acc[2][4][4];
#pragma unroll
    for (int mt = 0; mt < 2; mt++)
#pragma unroll
        for (int j = 0; j < 4; j++)
#pragma unroll
            for (int r = 0; r < 4; r++) acc[mt][j][r] = 0.0f;

    load_chunk(0, 0);
    load_chunk(1, 1);

    const int aoff0 = (wm * 32 + q) * 4 + cc;    // float index in A tile
    const int boff0 = (wn * 32 + q) * 4 + cc;    // float index in B tile

    for (int c = 0; c < NCHUNK; c++) {
        const int b = c % 3;
        asm volatile("cp.async.wait_group 1;" ::: "memory");
        __syncthreads();                         // raw[b] landed; prior mma done

        // -------- split pass: hi = mask13(x) in place, lo = x - hi --------
        {
            float4* raw = (float4*)(dsm + b * TILE_BYTES);
            float4* lo  = (float4*)(dsm + LO_OFF + (c & 1) * TILE_BYTES);
#pragma unroll
            for (int p = 0; p < 6; p++) {
                int v = tid + p * 256;
                float4 rv = raw[v];
                uint4  u  = *(uint4*)&rv;
                u.x &= 0xFFFFE000u; u.y &= 0xFFFFE000u;
                u.z &= 0xFFFFE000u; u.w &= 0xFFFFE000u;
                float4 hv = *(float4*)&u;
                float4 lv = make_float4(rv.x - hv.x, rv.y - hv.y,
                                        rv.z - hv.z, rv.w - hv.w);
                raw[v] = hv;
                lo[v]  = lv;
            }
        }
        if (c + 2 < NCHUNK) load_chunk(c + 2, (c + 2) % 3);
        else asm volatile("cp.async.commit_group;" ::: "memory");
        __syncthreads();                         // hi/lo visible

        // -------- MMA phase --------
        const uint32_t* hiA = (const uint32_t*)(dsm + b * TILE_BYTES);
        const uint32_t* hiB = hiA + (A_BYTES / 4);
        const uint32_t* loA = (const uint32_t*)(dsm + LO_OFF + (c & 1) * TILE_BYTES);
        const uint32_t* loB = loA + (A_BYTES / 4);

#pragma unroll
        for (int s = 0; s < 4; s++) {            // 4 x (k=8)
            const int ab = s * 1024 + aoff0;
            const int bb = s * 512  + boff0;
            uint32_t ah[2][4], al[2][4], bh[4][2], bl[4][2];
#pragma unroll
            for (int mt = 0; mt < 2; mt++) {
                int o = ab + mt * 64;
                ah[mt][0] = hiA[o];       ah[mt][1] = hiA[o + 32];
                ah[mt][2] = hiA[o + 512]; ah[mt][3] = hiA[o + 544];
                al[mt][0] = loA[o];       al[mt][1] = loA[o + 32];
                al[mt][2] = loA[o + 512]; al[mt][3] = loA[o + 544];
            }
#pragma unroll
            for (int j = 0; j < 4; j++) {
                int o = bb + j * 32;
                bh[j][0] = hiB[o]; bh[j][1] = hiB[o + 256];
                bl[j][0] = loB[o]; bl[j][1] = loB[o + 256];
            }
#pragma unroll
            for (int mt = 0; mt < 2; mt++)
#pragma unroll
                for (int j = 0; j < 4; j++) {
                    MMA(acc[mt][j], ah[mt], bh[j]);
                    MMA(acc[mt][j], ah[mt], bl[j]);
                    MMA(acc[mt][j], al[mt], bh[j]);
                }
        }
    }

    // -------- epilogue: accumulators -> smem logits, fused softmax/top-2 --------
    __syncthreads();
    float* ls = (float*)dsm;                     // logits[128][LPITCH]
#pragma unroll
    for (int mt = 0; mt < 2; mt++)
#pragma unroll
        for (int j = 0; j < 4; j++) {
            int row = wm * 32 + mt * 16 + q;
            int col = wn * 32 + j * 8 + 2 * cc;
            *(float2*)(ls + row * LPITCH + col)       = make_float2(acc[mt][j][0], acc[mt][j][1]);
            *(float2*)(ls + (row + 8) * LPITCH + col) = make_float2(acc[mt][j][2], acc[mt][j][3]);
        }
    __syncthreads();

    float* scores_out = out;
    float* w_out = out + (size_t)T * Edim;
    float* i_out = w_out + (size_t)T * 2;

    if (tid < TOKS) {
        const float* row = ls + tid * LPITCH;
        float m = -INFINITY;
#pragma unroll
        for (int e = 0; e < Edim; e++) m = fmaxf(m, row[e]);

        float Z = 0.0f;
        float v0=-INFINITY, v1=-INFINITY, v2=-INFINITY, v3=-INFINITY;
        int   i0=0, i1=0, i2=0, i3=0;
#pragma unroll
        for (int e = 0; e < Edim; e++) {
            float v = row[e];
            Z += expf(v - m);
            if (v > v0)      { v3=v2;i3=i2; v2=v1;i2=i1; v1=v0;i1=i0; v0=v;i0=e; }
            else if (v > v1) { v3=v2;i3=i2; v2=v1;i2=i1; v1=v;i1=e; }
            else if (v > v2) { v3=v2;i3=i2; v2=v;i2=e; }
            else if (v > v3) { v3=v;i3=e; }
        }
        s_max[tid] = m;
        s_inv[tid] = 1.0f / Z;

        float e0 = expf(v0 - m);
        float e1 = expf(v1 - m);
        float rs = 1.0f / (e0 + e1);
        size_t gt = (size_t)(tb + tid);
        w_out[gt * 2 + 0] = e0 * rs;
        w_out[gt * 2 + 1] = e1 * rs;
        i_out[gt * 2 + 0] = (float)i0;
        i_out[gt * 2 + 1] = (float)i1;

        // near-tie: flag for exact fp32 recomputation of the top-4 candidates
        if ((v0 - v1 < TAU) || (v1 - v2 < TAU)) {
            int slot = atomicAdd(&g_qcount, 1);
            g_qitems[slot] = make_int2((int)gt,
                i0 | (i1 << 6) | (i2 << 12) | (i3 << 18));
        }
    }
    __syncthreads();

#pragma unroll
    for (int p = 0; p < (TOKS * Edim) / 256; p++) {
        int idx = tid + p * 256;
        int t = idx >> 6, e = idx & 63;
        scores_out[(size_t)(tb + t) * Edim + e] =
            expf(ls[t * LPITCH + e] - s_max[t]) * s_inv[t];
    }
}

__global__ void zeroq_kernel() { g_qcount = 0; }

__global__ void fixup_kernel(const float* __restrict__ x, const float* __restrict__ W,
                             float* __restrict__ out, int T)
{
    float* w_out = out + (size_t)T * Edim;
    float* i_out = w_out + (size_t)T * 2;
    const int n    = g_qcount;
    const int gw   = (blockIdx.x * blockDim.x + threadIdx.x) >> 5;
    const int nw   = (gridDim.x * blockDim.x) >> 5;
    const int lane = threadIdx.x & 31;

    for (int it = gw; it < n; it += nw) {
        int2 qi = g_qitems[it];
        const int t = qi.x;
        const unsigned pk = (unsigned)qi.y;
        const int e0 = pk & 63, e1 = (pk>>6)&63, e2 = (pk>>12)&63, e3 = (pk>>18)&63;
        const float4* xr = (const float4*)(x + (size_t)t * Hdim);
        const float4* p0 = (const float4*)(W + (size_t)e0 * Hdim);
        const float4* p1 = (const float4*)(W + (size_t)e1 * Hdim);
        const float4* p2 = (const float4*)(W + (size_t)e2 * Hdim);
        const float4* p3 = (const float4*)(W + (size_t)e3 * Hdim);
        float a0=0, a1=0, a2=0, a3=0;
        for (int i = lane; i < Hdim/4; i += 32) {
            float4 xv = xr[i];
            float4 w;
            w = p0[i]; a0 += xv.x*w.x + xv.y*w.y + xv.z*w.z + xv.w*w.w;
            w = p1[i]; a1 += xv.x*w.x + xv.y*w.y + xv.z*w.z + xv.w*w.w;
            w = p2[i]; a2 += xv.x*w.x + xv.y*w.y + xv.z*w.z + xv.w*w.w;
            w = p3[i]; a3 += xv.x*w.x + xv.y*w.y + xv.z*w.z + xv.w*w.w;
        }
#pragma unroll
        for (int o = 16; o; o >>= 1) {
            a0 += __shfl_xor_sync(0xFFFFFFFFu, a0, o);
            a1 += __shfl_xor_sync(0xFFFFFFFFu, a1, o);
            a2 += __shfl_xor_sync(0xFFFFFFFFu, a2, o);
            a3 += __shfl_xor_sync(0xFFFFFFFFu, a3, o);
        }
        if (lane == 0) {
            float v[4]  = {a0, a1, a2, a3};
            int   id[4] = {e0, e1, e2, e3};
            int b0 = 0;
#pragma unroll
            for (int j = 1; j < 4; j++)
                if (v[j] > v[b0] || (v[j] == v[b0] && id[j] < id[b0])) b0 = j;
            int b1 = (b0 == 0) ? 1 : 0;
#pragma unroll
            for (int j = 0; j < 4; j++)
                if (j != b0 && (v[j] > v[b1] || (v[j] == v[b1] && id[j] < id[b1]))) b1 = j;
            float er  = __expf(v[b1] - v[b0]);
            float inv = 1.0f / (1.0f + er);
            w_out[(size_t)t*2 + 0] = inv;
            w_out[(size_t)t*2 + 1] = er * inv;
            i_out[(size_t)t*2 + 0] = (float)id[b0];
            i_out[(size_t)t*2 + 1] = (float)id[b1];
        }
    }
}

extern "C" void kernel_launch(void* const* d_in, const int* in_sizes, int n_in,
                              void* d_out, int out_size)
{
    const float* x = (const float*)d_in[0];
    const float* W = (const float*)d_in[1];
    float* out = (float*)d_out;
    const int T = in_sizes[0] / Hdim;            // 16384
    cudaFuncSetAttribute(router_mma, cudaFuncAttributeMaxDynamicSharedMemorySize, DYN_SMEM);
    zeroq_kernel<<<1, 1>>>();
    router_mma<<<T / TOKS, 256, DYN_SMEM>>>(x, W, out, T);
    fixup_kernel<<<64, 128>>>(x, W, out, T);
}

// round 7
// speedup vs baseline: 2.4619x; 2.1905x over previous
#include <cuda_runtime.h>
#include <math.h>
#include <stdint.h>

#define Hdim   4096
#define Edim   64
#define TOKS   128
#define KC     32                    // K elems per chunk
#define NCHUNK (Hdim / KC)           // 128
// bf16 chunk buffers: A hi 8K, A lo 8K, B hi 4K, B lo 4K = 24K per buffer
#define ABYTES   8192
#define BBYTES   4096
#define BUF_BYTES (2*ABYTES + 2*BBYTES)       // 24576
#define DYN_SMEM  (2 * BUF_BYTES)             // 49152
#define LPITCH 72
#define TAU 4e-3f

#define MMAB(d, a, b0_, b1_)                                                  \
    asm volatile("mma.sync.aligned.m16n8k16.row.col.f32.bf16.bf16.f32 "       \
                 "{%0,%1,%2,%3},{%4,%5,%6,%7},{%8,%9},{%0,%1,%2,%3};"         \
                 : "+f"((d)[0]), "+f"((d)[1]), "+f"((d)[2]), "+f"((d)[3])     \
                 : "r"((a)[0]), "r"((a)[1]), "r"((a)[2]), "r"((a)[3]),        \
                   "r"(b0_), "r"(b1_))

#define LDSM4(r, addr)                                                        \
    asm volatile("ldmatrix.sync.aligned.m8n8.x4.shared.b16 {%0,%1,%2,%3}, [%4];" \
                 : "=r"((r)[0]), "=r"((r)[1]), "=r"((r)[2]), "=r"((r)[3])     \
                 : "r"(addr))

__device__ int  g_qcount;
__device__ int2 g_qitems[16384];

__device__ __forceinline__ uint32_t packbf(float hi, float lo) {
    uint32_t r;
    asm("cvt.rn.bf16x2.f32 %0, %1, %2;" : "=r"(r) : "f"(hi), "f"(lo));
    return r;
}

__global__ __launch_bounds__(256)
void router_mma(const float* __restrict__ x, const float* __restrict__ W,
                float* __restrict__ out, int T)
{
    extern __shared__ __align__(16) char dsm[];
    __shared__ float s_max[TOKS];
    __shared__ float s_inv[TOKS];

    const int tid  = threadIdx.x;
    const int wid  = tid >> 5;
    const int lane = tid & 31;
    const int q    = lane >> 2;
    const int cc   = lane & 3;
    const int wm   = wid >> 1;           // 0..3 : 32-token warp tile
    const int wn   = wid & 1;            // 0..1 : 32-expert warp tile
    const int tb   = blockIdx.x * TOKS;

    const uint32_t sbase = (uint32_t)__cvta_generic_to_shared(dsm);

    const int rB = tid >> 3;             // loader row base
    const int s4 = tid & 7;              // loader 16B segment (k seg)

    // swizzled byte offset within a tile region for (row r, seg s4)
    auto soff = [&](int r) -> uint32_t {
        return (uint32_t)(r * 64 + ((((s4 >> 1) + (r >> 1)) & 3) << 4) + ((s4 & 1) << 3));
    };

    float4 ra[4]; float4 rb[2];

    auto ldg_chunk = [&](int c) {
        const int kb = c * KC + s4 * 4;
#pragma unroll
        for (int p = 0; p < 4; p++)
            ra[p] = *(const float4*)(x + (size_t)(tb + rB + 32 * p) * Hdim + kb);
#pragma unroll
        for (int p = 0; p < 2; p++)
            rb[p] = *(const float4*)(W + (size_t)(rB + 32 * p) * Hdim + kb);
    };

    auto split_sts = [&](int b) {
        char* buf = dsm + b * BUF_BYTES;
#pragma unroll
        for (int p = 0; p < 4; p++) {
            float4 f = ra[p];
            uint32_t h0 = packbf(f.y, f.x);
            uint32_t h1 = packbf(f.w, f.z);
            uint32_t l0 = packbf(f.y - __uint_as_float(h0 & 0xFFFF0000u),
                                 f.x - __uint_as_float(h0 << 16));
            uint32_t l1 = packbf(f.w - __uint_as_float(h1 & 0xFFFF0000u),
                                 f.z - __uint_as_float(h1 << 16));
            uint32_t o = soff(rB + 32 * p);
            *(uint2*)(buf + o)          = make_uint2(h0, h1);
            *(uint2*)(buf + ABYTES + o) = make_uint2(l0, l1);
        }
#pragma unroll
        for (int p = 0; p < 2; p++) {
            float4 f = rb[p];
            uint32_t h0 = packbf(f.y, f.x);
            uint32_t h1 = packbf(f.w, f.z);
            uint32_t l0 = packbf(f.y - __uint_as_float(h0 & 0xFFFF0000u),
                                 f.x - __uint_as_float(h0 << 16));
            uint32_t l1 = packbf(f.w - __uint_as_float(h1 & 0xFFFF0000u),
                                 f.z - __uint_as_float(h1 << 16));
            uint32_t o = soff(rB + 32 * p);
            *(uint2*)(buf + 2 * ABYTES + o)          = make_uint2(h0, h1);
            *(uint2*)(buf + 2 * ABYTES + BBYTES + o) = make_uint2(l0, l1);
        }
    };

    float acc[2][4][4];
#pragma unroll
    for (int mt = 0; mt < 2; mt++)
#pragma unroll
        for (int j = 0; j < 4; j++)
#pragma unroll
            for (int r = 0; r < 4; r++) acc[mt][j][r] = 0.0f;

    // ldmatrix per-lane rows (constant across chunks)
    const int arow = wm * 32 + (lane & 7) + ((lane >> 3) & 1) * 8;  // + mt*16
    const int brow = wn * 32 + lane;

    ldg_chunk(0);
    split_sts(0);
    ldg_chunk(1);
    __syncthreads();

    for (int c = 0; c < NCHUNK; c++) {
        const int b = c & 1;
        if (c + 1 < NCHUNK) split_sts((c + 1) & 1);
        if (c + 2 < NCHUNK) ldg_chunk(c + 2);

        const uint32_t Ah = sbase + b * BUF_BYTES;
        const uint32_t Al = Ah + ABYTES;
        const uint32_t Bh = Ah + 2 * ABYTES;
        const uint32_t Bl = Bh + BBYTES;

#pragma unroll
        for (int ks = 0; ks < 2; ks++) {
            const int au = 2 * ks + (lane >> 4);
            const uint32_t aoff = (uint32_t)(arow * 64 + (((au + (arow >> 1)) & 3) << 4));
            const uint32_t bo0  = (uint32_t)(brow * 64 + ((((2*ks)   + (brow >> 1)) & 3) << 4));
            const uint32_t bo1  = (uint32_t)(brow * 64 + ((((2*ks+1) + (brow >> 1)) & 3) << 4));

            uint32_t ah0[4], ah1[4], al0[4], al1[4];
            uint32_t bh0[4], bh1[4], bl0[4], bl1[4];
            LDSM4(ah0, Ah + aoff);
            LDSM4(ah1, Ah + aoff + 1024);
            LDSM4(al0, Al + aoff);
            LDSM4(al1, Al + aoff + 1024);
            LDSM4(bh0, Bh + bo0);
            LDSM4(bh1, Bh + bo1);
            LDSM4(bl0, Bl + bo0);
            LDSM4(bl1, Bl + bo1);

#pragma unroll
            for (int j = 0; j < 4; j++) {
                MMAB(acc[0][j], ah0, bh0[j], bh1[j]);
                MMAB(acc[1][j], ah1, bh0[j], bh1[j]);
                MMAB(acc[0][j], ah0, bl0[j], bl1[j]);
                MMAB(acc[1][j], ah1, bl0[j], bl1[j]);
                MMAB(acc[0][j], al0, bh0[j], bh1[j]);
                MMAB(acc[1][j], al1, bh0[j], bh1[j]);
            }
        }
        __syncthreads();
    }

    // -------- epilogue: logits -> smem, fused softmax/top-2 + near-tie queue --------
    float* ls = (float*)dsm;
#pragma unroll
    for (int mt = 0; mt < 2; mt++)
#pragma unroll
        for (int j = 0; j < 4; j++) {
            int row = wm * 32 + mt * 16 + q;
            int col = wn * 32 + j * 8 + 2 * cc;
            *(float2*)(ls + row * LPITCH + col)       = make_float2(acc[mt][j][0], acc[mt][j][1]);
            *(float2*)(ls + (row + 8) * LPITCH + col) = make_float2(acc[mt][j][2], acc[mt][j][3]);
        }
    __syncthreads();

    float* scores_out = out;
    float* w_out = out + (size_t)T * Edim;
    float* i_out = w_out + (size_t)T * 2;

    if (tid < TOKS) {
        const float* row = ls + tid * LPITCH;
        float m = -INFINITY;
#pragma unroll
        for (int e = 0; e < Edim; e++) m = fmaxf(m, row[e]);

        float Z = 0.0f;
        float v0=-INFINITY, v1=-INFINITY, v2=-INFINITY, v3=-INFINITY;
        int   i0=0, i1=0, i2=0, i3=0;
#pragma unroll
        for (int e = 0; e < Edim; e++) {
            float v = row[e];
            Z += expf(v - m);
            if (v > v0)      { v3=v2;i3=i2; v2=v1;i2=i1; v1=v0;i1=i0; v0=v;i0=e; }
            else if (v > v1) { v3=v2;i3=i2; v2=v1;i2=i1; v1=v;i1=e; }
            else if (v > v2) { v3=v2;i3=i2; v2=v;i2=e; }
            else if (v > v3) { v3=v;i3=e; }
        }
        s_max[tid] = m;
        s_inv[tid] = 1.0f / Z;

        float e0 = expf(v0 - m);
        float e1 = expf(v1 - m);
        float rs = 1.0f / (e0 + e1);
        size_t gt = (size_t)(tb + tid);
        w_out[gt * 2 + 0] = e0 * rs;
        w_out[gt * 2 + 1] = e1 * rs;
        i_out[gt * 2 + 0] = (float)i0;
        i_out[gt * 2 + 1] = (float)i1;

        if ((v0 - v1 < TAU) || (v1 - v2 < TAU)) {
            int slot = atomicAdd(&g_qcount, 1);
            g_qitems[slot] = make_int2((int)gt, i0 | (i1 << 6) | (i2 << 12) | (i3 << 18));
        }
    }
    __syncthreads();

#pragma unroll
    for (int p = 0; p < (TOKS * Edim) / 256; p++) {
        int idx = tid + p * 256;
        int t = idx >> 6, e = idx & 63;
        scores_out[(size_t)(tb + t) * Edim + e] =
            expf(ls[t * LPITCH + e] - s_max[t]) * s_inv[t];
    }
}

__global__ void zeroq_kernel() { g_qcount = 0; }

__global__ void fixup_kernel(const float* __restrict__ x, const float* __restrict__ W,
                             float* __restrict__ out, int T)
{
    float* w_out = out + (size_t)T * Edim;
    float* i_out = w_out + (size_t)T * 2;
    const int n    = g_qcount;
    const int gw   = (blockIdx.x * blockDim.x + threadIdx.x) >> 5;
    const int nw   = (gridDim.x * blockDim.x) >> 5;
    const int lane = threadIdx.x & 31;

    for (int it = gw; it < n; it += nw) {
        int2 qi = g_qitems[it];
        const int t = qi.x;
        const unsigned pk = (unsigned)qi.y;
        const int e0 = pk & 63, e1 = (pk>>6)&63, e2 = (pk>>12)&63, e3 = (pk>>18)&63;
        const float4* xr = (const float4*)(x + (size_t)t * Hdim);
        const float4* p0 = (const float4*)(W + (size_t)e0 * Hdim);
        const float4* p1 = (const float4*)(W + (size_t)e1 * Hdim);
        const float4* p2 = (const float4*)(W + (size_t)e2 * Hdim);
        const float4* p3 = (const float4*)(W + (size_t)e3 * Hdim);
        float a0=0, a1=0, a2=0, a3=0;
        for (int i = lane; i < Hdim/4; i += 32) {
            float4 xv = xr[i];
            float4 w;
            w = p0[i]; a0 += xv.x*w.x + xv.y*w.y + xv.z*w.z + xv.w*w.w;
            w = p1[i]; a1 += xv.x*w.x + xv.y*w.y + xv.z*w.z + xv.w*w.w;
            w = p2[i]; a2 += xv.x*w.x + xv.y*w.y + xv.z*w.z + xv.w*w.w;
            w = p3[i]; a3 += xv.x*w.x + xv.y*w.y + xv.z*w.z + xv.w*w.w;
        }
#pragma unroll
        for (int o = 16; o; o >>= 1) {
            a0 += __shfl_xor_sync(0xFFFFFFFFu, a0, o);
            a1 += __shfl_xor_sync(0xFFFFFFFFu, a1, o);
            a2 += __shfl_xor_sync(0xFFFFFFFFu, a2, o);
            a3 += __shfl_xor_sync(0xFFFFFFFFu, a3, o);
        }
        if (lane == 0) {
            float v[4]  = {a0, a1, a2, a3};
            int   id[4] = {e0, e1, e2, e3};
            int b0 = 0;
#pragma unroll
            for (int j = 1; j < 4; j++)
                if (v[j] > v[b0] || (v[j] == v[b0] && id[j] < id[b0])) b0 = j;
            int b1 = (b0 == 0) ? 1 : 0;
#pragma unroll
            for (int j = 0; j < 4; j++)
                if (j != b0 && (v[j] > v[b1] || (v[j] == v[b1] && id[j] < id[b1]))) b1 = j;
            float er  = __expf(v[b1] - v[b0]);
            float inv = 1.0f / (1.0f + er);
            w_out[(size_t)t*2 + 0] = inv;
            w_out[(size_t)t*2 + 1] = er * inv;
            i_out[(size_t)t*2 + 0] = (float)id[b0];
            i_out[(size_t)t*2 + 1] = (float)id[b1];
        }
    }
}

extern "C" void kernel_launch(void* const* d_in, const int* in_sizes, int n_in,
                              void* d_out, int out_size)
{
    const float* x = (const float*)d_in[0];
    const float* W = (const float*)d_in[1];
    float* out = (float*)d_out;
    const int T = in_sizes[0] / Hdim;            // 16384
    cudaFuncSetAttribute(router_mma, cudaFuncAttributeMaxDynamicSharedMemorySize, DYN_SMEM);
    zeroq_kernel<<<1, 1>>>();
    router_mma<<<T / TOKS, 256, DYN_SMEM>>>(x, W, out, T);
    fixup_kernel<<<64, 128>>>(x, W, out, T);
}